// round 12
// baseline (speedup 1.0000x reference)
#include <cuda_runtime.h>
#include <cuda_fp16.h>
#include <cstdint>

// ============================================================================
// HelixMemory (R10 GEMM + uniformly interleaved copy blocks):
//   out[b, 0:254]      = cm[r]   = memory[2r+2] @ F0 + memory[2r+3] @ F1
//   out[b, 254:510]    = cx[b,t] = x[b,2t] @ F0 + x[b,2t+1] @ F1
//   out[b, 510:2046]   = memory[1022:2558]
//   out[b, 2046:2558]  = x[b]
// conv_AB: inputs||memory-rows -> g_Ah fp16 (+x passthrough writes)
// conv_filters: filters -> g_Bt[n][k] fp16
// mega: 792 blocks, every 3rd block is a memory-broadcast copy CTA (so copy
//       DRAM traffic spreads across the whole GEMM timeline instead of
//       cramming into the final wave); the rest are the proven 3-stage
//       cp.async + ldmatrix + m16n8k16 GEMM tiles.
// ============================================================================

namespace {
constexpr int D_       = 1024;
constexpr int KDIM     = 2048;
constexpr int OUT_ROWS = 2558;
constexpr int CM_ROWS  = 254;
constexpr int BATCH    = 32;
constexpr int SEQ      = 512;

constexpr int M_ROWS = BATCH * 256 + 256;        // 8448 A rows

constexpr int BM = 128, BN = 128, BK = 64;       // BK in fp16 elements
constexpr int STAGES = 3;
constexpr int KT = KDIM / BK;                    // 32

constexpr int PITCH_H  = BK + 8;                 // 72 halves = 144 B pitch
constexpr int TILE_H   = BM * PITCH_H;           // 9216 halves
constexpr int STAGE_H  = 2 * TILE_H;             // A + B
constexpr int SMEM_BYTES = STAGES * STAGE_H * 2; // 110592 B -> occ 2

constexpr int GEMM_BLOCKS  = 8 * 66;             // 528
constexpr int COPY_CTAS    = 264;
constexpr int TOTAL_BLOCKS = GEMM_BLOCKS + COPY_CTAS;  // 792

// copy space: memory-tail broadcast (float4 units)
constexpr int BCST_PER_B = 1536 * D_ / 4;                          // 393216
constexpr int BCST_F4    = BATCH * BCST_PER_B;                     // 12,582,912
constexpr int COPY_CHUNK = (BCST_F4 + COPY_CTAS - 1) / COPY_CTAS;  // 47663
}

__device__ __align__(128) __half g_Ah[M_ROWS * KDIM];  // 34.6 MB fp16 A
__device__ __align__(128) __half g_Bt[D_ * KDIM];      // 4 MB filters^T [n][k]

// ---------------------------------------------------------------------------
__device__ __forceinline__ uint32_t smem_u32(const void* p) {
    uint32_t a;
    asm("{ .reg .u64 t; cvta.to.shared.u64 t, %1; cvt.u32.u64 %0, t; }" : "=r"(a) : "l"(p));
    return a;
}
__device__ __forceinline__ void cp16(uint32_t s, const void* g) {
    asm volatile("cp.async.cg.shared.global [%0], [%1], 16;" :: "r"(s), "l"(g));
}
__device__ __forceinline__ void ldsm_x4(uint32_t* r, uint32_t addr) {
    asm volatile("ldmatrix.sync.aligned.m8n8.x4.shared.b16 {%0,%1,%2,%3}, [%4];"
                 : "=r"(r[0]), "=r"(r[1]), "=r"(r[2]), "=r"(r[3]) : "r"(addr));
}
__device__ __forceinline__ void mma_f16(float* c, const uint32_t* a, const uint32_t* b) {
    asm volatile(
        "mma.sync.aligned.m16n8k16.row.col.f32.f16.f16.f32 "
        "{%0,%1,%2,%3}, {%4,%5,%6,%7}, {%8,%9}, {%0,%1,%2,%3};"
        : "+f"(c[0]), "+f"(c[1]), "+f"(c[2]), "+f"(c[3])
        : "r"(a[0]), "r"(a[1]), "r"(a[2]), "r"(a[3]), "r"(b[0]), "r"(b[1]));
}
__device__ __forceinline__ uint32_t pack_h2(float x, float y) {
    __half2 h = __floats2half2_rn(x, y);
    return *reinterpret_cast<uint32_t*>(&h);
}

// ---------------------------------------------------------------------------
// conv_AB: g_Ah rows [0,8192) <- inputs (also writes x passthrough to out),
//          rows [8192,8448) <- memory[2:514]
// ---------------------------------------------------------------------------
__global__ __launch_bounds__(256) void conv_AB(
    const float* __restrict__ inputs, const float* __restrict__ memory,
    float* __restrict__ out)
{
    constexpr int IN_F4 = BATCH * SEQ * D_ / 4;         // 4,194,304
    constexpr int TOTAL = M_ROWS * KDIM / 4;            // 4,325,376
    uint2* ah = reinterpret_cast<uint2*>(g_Ah);
    const float4* in4  = reinterpret_cast<const float4*>(inputs);
    const float4* mem4 = reinterpret_cast<const float4*>(memory + 2 * D_);
    float4* out4 = reinterpret_cast<float4*>(out);

    for (int idx = blockIdx.x * blockDim.x + threadIdx.x; idx < TOTAL;
         idx += gridDim.x * blockDim.x) {
        float4 v;
        if (idx < IN_F4) {
            v = in4[idx];
            const int b = idx >> 17;                    // / 131072
            const int rem = idx & 131071;
            out4[(size_t)b * (OUT_ROWS * D_ / 4) + 2046 * (D_ / 4) + rem] = v;
        } else {
            v = mem4[idx - IN_F4];
        }
        ah[idx] = make_uint2(pack_h2(v.x, v.y), pack_h2(v.z, v.w));
    }
}

// ---------------------------------------------------------------------------
// conv_filters: g_Bt[n][k] = fp16(F[k][n])
// ---------------------------------------------------------------------------
__global__ __launch_bounds__(256) void conv_filters(const float* __restrict__ F)
{
    __shared__ float tile[64][33];
    const int n0 = blockIdx.x * 32;
    const int k0 = blockIdx.y * 64;
    const int tx = threadIdx.x, ty = threadIdx.y;       // 32 x 8
    #pragma unroll
    for (int i = ty; i < 64; i += 8)
        tile[i][tx] = F[(size_t)(k0 + i) * D_ + n0 + tx];
    __syncthreads();
    uint32_t* bt = reinterpret_cast<uint32_t*>(g_Bt);
    #pragma unroll
    for (int i = ty; i < 32; i += 8)
        bt[(size_t)(n0 + i) * (KDIM / 2) + k0 / 2 + tx] =
            pack_h2(tile[2 * tx][i], tile[2 * tx + 1][i]);
}

// ---------------------------------------------------------------------------
// copy CTA body: out[b, 510:2046] = memory[1022:2558]; unroll-8 for MLP.
// ---------------------------------------------------------------------------
__device__ __forceinline__ void copy_body(
    int cid, const float* __restrict__ memory, float* __restrict__ out)
{
    const float4* mem4 = reinterpret_cast<const float4*>(memory) + 1022 * (D_ / 4);
    float4*       out4 = reinterpret_cast<float4*>(out);

    const int base = cid * COPY_CHUNK;
    const int end  = (base + COPY_CHUNK < BCST_F4) ? base + COPY_CHUNK : BCST_F4;

    for (int t = base + threadIdx.x; t < end; t += 256 * 8) {
        float4 v[8];
        size_t dj[8];
        bool ok[8];
        #pragma unroll
        for (int u = 0; u < 8; ++u) {
            const int idx = t + u * 256;
            ok[u] = (idx < end);
            if (ok[u]) {
                const int b = idx / BCST_PER_B;
                const int rem = idx - b * BCST_PER_B;
                v[u]  = mem4[rem];
                dj[u] = (size_t)b * (OUT_ROWS * D_ / 4) + 510 * (D_ / 4) + rem;
            }
        }
        #pragma unroll
        for (int u = 0; u < 8; ++u)
            if (ok[u]) out4[dj[u]] = v[u];
    }
}

// ---------------------------------------------------------------------------
// mega: every 3rd block = copy CTA (uniformly interleaved so copy DRAM
// traffic spreads over the full GEMM timeline); others = GEMM tiles.
// ---------------------------------------------------------------------------
__global__ __launch_bounds__(256, 2) void mega(
    const float* __restrict__ memory, float* __restrict__ out)
{
    const int blk = blockIdx.x;
    const int r3  = blk % 3;
    if (r3 == 2) {                              // copy CTA (1 in 3)
        copy_body(blk / 3, memory, out);
        return;
    }
    const int gid = (blk / 3) * 2 + r3;         // 0..527
    const int bm = gid >> 3;                    // 0..65
    const int bn = gid & 7;
    const int n0 = bn * BN;

    extern __shared__ __half smem_h[];
    const uint32_t sbase = smem_u32(smem_h);

    const int tid  = threadIdx.x;
    const int wid  = tid >> 5;
    const int lane = tid & 31;
    const int g    = lane >> 2;
    const int t    = lane & 3;
    const int wm   = wid & 3;                   // 4 warps x 32 rows
    const int wn   = wid >> 2;                  // 2 warps x 64 cols

    // ldmatrix lane->row mappings
    const int a_row = lane & 15;                // m within 16
    const int a_k   = (lane >> 4) << 3;         // k offset 0/8
    const int b_row = (lane & 7) + ((lane >> 4) << 3);   // n within 16
    const int b_k   = ((lane >> 3) & 1) << 3;   // k offset 0/8

    const uint32_t aoff0 = (uint32_t)((wm * 32 + a_row) * PITCH_H + a_k) * 2;
    const uint32_t boff0 = (uint32_t)TILE_H * 2 +
                           (uint32_t)((wn * 64 + b_row) * PITCH_H + b_k) * 2;

    const __half* Abase = g_Ah + (size_t)bm * BM * KDIM;

    auto issue = [&](int kt) {
        const int s = kt % STAGES;
        const uint32_t sA = sbase + (uint32_t)(s * STAGE_H) * 2;
        const uint32_t sB = sA + (uint32_t)TILE_H * 2;
        const int k0 = kt * BK;
        #pragma unroll
        for (int i = 0; i < 4; ++i) {           // 1024 16B chunks per tile
            const int q   = tid + 256 * i;
            const int row = q >> 3;
            const int c   = q & 7;
            cp16(sA + (uint32_t)(row * PITCH_H + c * 8) * 2,
                 Abase + (size_t)row * KDIM + k0 + c * 8);
            cp16(sB + (uint32_t)(row * PITCH_H + c * 8) * 2,
                 g_Bt + (size_t)(n0 + row) * KDIM + k0 + c * 8);
        }
        asm volatile("cp.async.commit_group;" ::: "memory");
    };

    float c[2][8][4] = {};

    issue(0);
    issue(1);

    for (int kt = 0; kt < KT; ++kt) {
        asm volatile("cp.async.wait_group 1;" ::: "memory");
        __syncthreads();

        if (kt + STAGES - 1 < KT) issue(kt + STAGES - 1);

        const int s = kt % STAGES;
        const uint32_t stg = sbase + (uint32_t)(s * STAGE_H) * 2;

        #pragma unroll
        for (int ks = 0; ks < 4; ++ks) {        // 4 x k16 = BK 64
            const uint32_t kb = (uint32_t)(ks * 16) * 2;   // k byte offset

            uint32_t a[2][4];
            #pragma unroll
            for (int mt = 0; mt < 2; ++mt)
                ldsm_x4(a[mt], stg + aoff0 + (uint32_t)(mt * 16 * PITCH_H) * 2 + kb);

            uint32_t bf[8][2];
            #pragma unroll
            for (int nb = 0; nb < 4; ++nb) {    // 4 x n16 = 64 cols
                uint32_t r[4];
                ldsm_x4(r, stg + boff0 + (uint32_t)(nb * 16 * PITCH_H) * 2 + kb);
                bf[2 * nb][0]     = r[0];
                bf[2 * nb][1]     = r[1];
                bf[2 * nb + 1][0] = r[2];
                bf[2 * nb + 1][1] = r[3];
            }
            #pragma unroll
            for (int mt = 0; mt < 2; ++mt)
                #pragma unroll
                for (int nt = 0; nt < 8; ++nt)
                    mma_f16(c[mt][nt], a[mt], bf[nt]);
        }
        __syncthreads();
    }

    // ---- epilogue -----------------------------------------------------------
    #pragma unroll
    for (int mt = 0; mt < 2; ++mt) {
        #pragma unroll
        for (int half = 0; half < 2; ++half) {
            const int rloc = wm * 32 + mt * 16 + half * 8 + g;
            if (bm < 64) {
                const int rr = bm * BM + rloc;
                const int b = rr >> 8, tt = rr & 255;
                float* dst = out + ((size_t)b * OUT_ROWS + 254 + tt) * D_ + n0 + wn * 64;
                #pragma unroll
                for (int nt = 0; nt < 8; ++nt) {
                    float2 v = make_float2(c[mt][nt][half * 2], c[mt][nt][half * 2 + 1]);
                    *reinterpret_cast<float2*>(dst + nt * 8 + t * 2) = v;
                }
            } else {
                const int rr = (bm - 64) * BM + rloc;   // compressed-memory row
                if (rr < CM_ROWS) {
                    float* dst0 = out + (size_t)rr * D_ + n0 + wn * 64;
                    #pragma unroll
                    for (int nt = 0; nt < 8; ++nt) {
                        float2 v = make_float2(c[mt][nt][half * 2], c[mt][nt][half * 2 + 1]);
                        float* dp = dst0 + nt * 8 + t * 2;
                        for (int b = 0; b < BATCH; ++b)
                            *reinterpret_cast<float2*>(dp + (size_t)b * OUT_ROWS * D_) = v;
                    }
                }
            }
        }
    }
}

// ---------------------------------------------------------------------------
extern "C" void kernel_launch(void* const* d_in, const int* in_sizes, int n_in,
                              void* d_out, int out_size)
{
    const float* inputs  = (const float*)d_in[0];  // (32, 512, 1024)
    const float* memory  = (const float*)d_in[1];  // (2558, 1024)
    const float* filters = (const float*)d_in[2];  // (2, 1024, 1024)
    float* out = (float*)d_out;                    // (32, 2558, 1024)

    cudaFuncSetAttribute(mega, cudaFuncAttributeMaxDynamicSharedMemorySize,
                         SMEM_BYTES);

    conv_AB<<<148 * 8, 256>>>(inputs, memory, out);
    conv_filters<<<dim3(D_ / 32, KDIM / 64), dim3(32, 8)>>>(filters);

    mega<<<TOTAL_BLOCKS, 256, SMEM_BYTES>>>(memory, out);
}

// round 13
// speedup vs baseline: 1.1000x; 1.1000x over previous
#include <cuda_runtime.h>
#include <cuda_fp16.h>
#include <cstdint>

// ============================================================================
// HelixMemory (best-known config + sync-removal + merged prep):
//   out[b, 0:254]      = cm[r]   = memory[2r+2] @ F0 + memory[2r+3] @ F1
//   out[b, 254:510]    = cx[b,t] = x[b,2t] @ F0 + x[b,2t+1] @ F1
//   out[b, 510:2046]   = memory[1022:2558]
//   out[b, 2046:2558]  = x[b]
// kernel 1: prep (merged): blocks [0,1184) convert inputs||memory-rows ->
//           g_Ah fp16 (+x passthrough writes); blocks [1184,2208) build
//           g_Bt[n][k] = fp16(filters^T).
// kernel 2: mega: blocks [0,528) = GEMM tiles (3-stage cp.async + ldmatrix +
//           m16n8k16, ONE barrier per kt iteration; cm rows broadcast to all
//           32 batches in the epilogue); blocks [528,792) = tail copy CTAs
//           (memory-tail broadcast, unroll-8) backfilling wave-2 slots.
// ============================================================================

namespace {
constexpr int D_       = 1024;
constexpr int KDIM     = 2048;
constexpr int OUT_ROWS = 2558;
constexpr int CM_ROWS  = 254;
constexpr int BATCH    = 32;
constexpr int SEQ      = 512;

constexpr int M_ROWS = BATCH * 256 + 256;        // 8448 A rows

constexpr int BM = 128, BN = 128, BK = 64;       // BK in fp16 elements
constexpr int STAGES = 3;
constexpr int KT = KDIM / BK;                    // 32

constexpr int PITCH_H  = BK + 8;                 // 72 halves = 144 B pitch
constexpr int TILE_H   = BM * PITCH_H;           // 9216 halves
constexpr int STAGE_H  = 2 * TILE_H;             // A + B
constexpr int SMEM_BYTES = STAGES * STAGE_H * 2; // 110592 B -> occ 2

constexpr int GEMM_BLOCKS  = 8 * 66;             // 528
constexpr int COPY_CTAS    = 264;
constexpr int TOTAL_BLOCKS = GEMM_BLOCKS + COPY_CTAS;  // 792

// prep kernel block split
constexpr int AB_BLOCKS   = 1184;                // conv_AB part
constexpr int FILT_BLOCKS = (D_ / 32) * (KDIM / 64);   // 1024
constexpr int PREP_BLOCKS = AB_BLOCKS + FILT_BLOCKS;   // 2208

// copy space: memory-tail broadcast (float4 units)
constexpr int BCST_PER_B = 1536 * D_ / 4;                          // 393216
constexpr int BCST_F4    = BATCH * BCST_PER_B;                     // 12,582,912
constexpr int COPY_CHUNK = (BCST_F4 + COPY_CTAS - 1) / COPY_CTAS;  // 47663
}

__device__ __align__(128) __half g_Ah[M_ROWS * KDIM];  // 34.6 MB fp16 A
__device__ __align__(128) __half g_Bt[D_ * KDIM];      // 4 MB filters^T [n][k]

// ---------------------------------------------------------------------------
__device__ __forceinline__ uint32_t smem_u32(const void* p) {
    uint32_t a;
    asm("{ .reg .u64 t; cvta.to.shared.u64 t, %1; cvt.u32.u64 %0, t; }" : "=r"(a) : "l"(p));
    return a;
}
__device__ __forceinline__ void cp16(uint32_t s, const void* g) {
    asm volatile("cp.async.cg.shared.global [%0], [%1], 16;" :: "r"(s), "l"(g));
}
__device__ __forceinline__ void ldsm_x4(uint32_t* r, uint32_t addr) {
    asm volatile("ldmatrix.sync.aligned.m8n8.x4.shared.b16 {%0,%1,%2,%3}, [%4];"
                 : "=r"(r[0]), "=r"(r[1]), "=r"(r[2]), "=r"(r[3]) : "r"(addr));
}
__device__ __forceinline__ void mma_f16(float* c, const uint32_t* a, const uint32_t* b) {
    asm volatile(
        "mma.sync.aligned.m16n8k16.row.col.f32.f16.f16.f32 "
        "{%0,%1,%2,%3}, {%4,%5,%6,%7}, {%8,%9}, {%0,%1,%2,%3};"
        : "+f"(c[0]), "+f"(c[1]), "+f"(c[2]), "+f"(c[3])
        : "r"(a[0]), "r"(a[1]), "r"(a[2]), "r"(a[3]), "r"(b[0]), "r"(b[1]));
}
__device__ __forceinline__ uint32_t pack_h2(float x, float y) {
    __half2 h = __floats2half2_rn(x, y);
    return *reinterpret_cast<uint32_t*>(&h);
}

// ---------------------------------------------------------------------------
// prep (merged): blocks [0,1184): conv_AB; blocks [1184,2208): conv_filters
// ---------------------------------------------------------------------------
__global__ __launch_bounds__(256) void prep(
    const float* __restrict__ inputs, const float* __restrict__ memory,
    const float* __restrict__ F, float* __restrict__ out)
{
    const int blk = blockIdx.x;
    const int tid = threadIdx.x;

    if (blk < AB_BLOCKS) {
        // ---- conv_AB: g_Ah rows [0,8192) <- inputs (+passthrough),
        //               rows [8192,8448) <- memory[2:514] ----
        constexpr int IN_F4 = BATCH * SEQ * D_ / 4;     // 4,194,304
        constexpr int TOTAL = M_ROWS * KDIM / 4;        // 4,325,376
        uint2* ah = reinterpret_cast<uint2*>(g_Ah);
        const float4* in4  = reinterpret_cast<const float4*>(inputs);
        const float4* mem4 = reinterpret_cast<const float4*>(memory + 2 * D_);
        float4* out4 = reinterpret_cast<float4*>(out);

        for (int idx = blk * 256 + tid; idx < TOTAL; idx += AB_BLOCKS * 256) {
            float4 v;
            if (idx < IN_F4) {
                v = in4[idx];
                const int b = idx >> 17;                // / 131072
                const int rem = idx & 131071;
                out4[(size_t)b * (OUT_ROWS * D_ / 4) + 2046 * (D_ / 4) + rem] = v;
            } else {
                v = mem4[idx - IN_F4];
            }
            ah[idx] = make_uint2(pack_h2(v.x, v.y), pack_h2(v.z, v.w));
        }
    } else {
        // ---- conv_filters: g_Bt[n][k] = fp16(F[k][n]) ----
        __shared__ float tile[64][33];
        const int cid = blk - AB_BLOCKS;                // 0..1023
        const int n0 = (cid & 31) * 32;
        const int k0 = (cid >> 5) * 64;
        const int tx = tid & 31, ty = tid >> 5;         // 32 x 8
        #pragma unroll
        for (int i = ty; i < 64; i += 8)
            tile[i][tx] = F[(size_t)(k0 + i) * D_ + n0 + tx];
        __syncthreads();
        uint32_t* bt = reinterpret_cast<uint32_t*>(g_Bt);
        #pragma unroll
        for (int i = ty; i < 32; i += 8)
            bt[(size_t)(n0 + i) * (KDIM / 2) + k0 / 2 + tx] =
                pack_h2(tile[2 * tx][i], tile[2 * tx + 1][i]);
    }
}

// ---------------------------------------------------------------------------
// copy CTA body: out[b, 510:2046] = memory[1022:2558]; unroll-8 for MLP.
// ---------------------------------------------------------------------------
__device__ __forceinline__ void copy_body(
    int cid, const float* __restrict__ memory, float* __restrict__ out)
{
    const float4* mem4 = reinterpret_cast<const float4*>(memory) + 1022 * (D_ / 4);
    float4*       out4 = reinterpret_cast<float4*>(out);

    const int base = cid * COPY_CHUNK;
    const int end  = (base + COPY_CHUNK < BCST_F4) ? base + COPY_CHUNK : BCST_F4;

    for (int t = base + threadIdx.x; t < end; t += 256 * 8) {
        float4 v[8];
        size_t dj[8];
        bool ok[8];
        #pragma unroll
        for (int u = 0; u < 8; ++u) {
            const int idx = t + u * 256;
            ok[u] = (idx < end);
            if (ok[u]) {
                const int b = idx / BCST_PER_B;
                const int rem = idx - b * BCST_PER_B;
                v[u]  = mem4[rem];
                dj[u] = (size_t)b * (OUT_ROWS * D_ / 4) + 510 * (D_ / 4) + rem;
            }
        }
        #pragma unroll
        for (int u = 0; u < 8; ++u)
            if (ok[u]) out4[dj[u]] = v[u];
    }
}

// ---------------------------------------------------------------------------
// mega: blocks [0,528) = GEMM tiles; [528,792) = copy CTAs (tail-filling).
// ---------------------------------------------------------------------------
__global__ __launch_bounds__(256, 2) void mega(
    const float* __restrict__ memory, float* __restrict__ out)
{
    const int blk = blockIdx.x;
    if (blk >= GEMM_BLOCKS) {
        copy_body(blk - GEMM_BLOCKS, memory, out);
        return;
    }
    const int bm = blk >> 3;                    // 0..65
    const int bn = blk & 7;
    const int n0 = bn * BN;

    extern __shared__ __half smem_h[];
    const uint32_t sbase = smem_u32(smem_h);

    const int tid  = threadIdx.x;
    const int wid  = tid >> 5;
    const int lane = tid & 31;
    const int g    = lane >> 2;
    const int t    = lane & 3;
    const int wm   = wid & 3;                   // 4 warps x 32 rows
    const int wn   = wid >> 2;                  // 2 warps x 64 cols

    // ldmatrix lane->row mappings
    const int a_row = lane & 15;                // m within 16
    const int a_k   = (lane >> 4) << 3;         // k offset 0/8
    const int b_row = (lane & 7) + ((lane >> 4) << 3);   // n within 16
    const int b_k   = ((lane >> 3) & 1) << 3;   // k offset 0/8

    const uint32_t aoff0 = (uint32_t)((wm * 32 + a_row) * PITCH_H + a_k) * 2;
    const uint32_t boff0 = (uint32_t)TILE_H * 2 +
                           (uint32_t)((wn * 64 + b_row) * PITCH_H + b_k) * 2;

    const __half* Abase = g_Ah + (size_t)bm * BM * KDIM;

    auto issue = [&](int kt) {
        const int s = kt % STAGES;
        const uint32_t sA = sbase + (uint32_t)(s * STAGE_H) * 2;
        const uint32_t sB = sA + (uint32_t)TILE_H * 2;
        const int k0 = kt * BK;
        #pragma unroll
        for (int i = 0; i < 4; ++i) {           // 1024 16B chunks per tile
            const int q   = tid + 256 * i;
            const int row = q >> 3;
            const int c   = q & 7;
            cp16(sA + (uint32_t)(row * PITCH_H + c * 8) * 2,
                 Abase + (size_t)row * KDIM + k0 + c * 8);
            cp16(sB + (uint32_t)(row * PITCH_H + c * 8) * 2,
                 g_Bt + (size_t)(n0 + row) * KDIM + k0 + c * 8);
        }
        asm volatile("cp.async.commit_group;" ::: "memory");
    };

    float c[2][8][4] = {};

    issue(0);
    issue(1);

    for (int kt = 0; kt < KT; ++kt) {
        asm volatile("cp.async.wait_group 1;" ::: "memory");
        // Single barrier per iteration: separates iter kt-1's smem reads from
        // this iteration's issue into stage (kt+2)%3 == (kt-1)%3, and makes
        // stage kt's cp.async data (own-group waited above) visible to all.
        __syncthreads();

        if (kt + STAGES - 1 < KT) issue(kt + STAGES - 1);

        const int s = kt % STAGES;
        const uint32_t stg = sbase + (uint32_t)(s * STAGE_H) * 2;

        #pragma unroll
        for (int ks = 0; ks < 4; ++ks) {        // 4 x k16 = BK 64
            const uint32_t kb = (uint32_t)(ks * 16) * 2;   // k byte offset

            uint32_t a[2][4];
            #pragma unroll
            for (int mt = 0; mt < 2; ++mt)
                ldsm_x4(a[mt], stg + aoff0 + (uint32_t)(mt * 16 * PITCH_H) * 2 + kb);

            uint32_t bf[8][2];
            #pragma unroll
            for (int nb = 0; nb < 4; ++nb) {    // 4 x n16 = 64 cols
                uint32_t r[4];
                ldsm_x4(r, stg + boff0 + (uint32_t)(nb * 16 * PITCH_H) * 2 + kb);
                bf[2 * nb][0]     = r[0];
                bf[2 * nb][1]     = r[1];
                bf[2 * nb + 1][0] = r[2];
                bf[2 * nb + 1][1] = r[3];
            }
            #pragma unroll
            for (int mt = 0; mt < 2; ++mt)
                #pragma unroll
                for (int nt = 0; nt < 8; ++nt)
                    mma_f16(c[mt][nt], a[mt], bf[nt]);
        }
        // (trailing __syncthreads removed — top-of-loop barrier suffices)
    }

    // ---- epilogue -----------------------------------------------------------
    #pragma unroll
    for (int mt = 0; mt < 2; ++mt) {
        #pragma unroll
        for (int half = 0; half < 2; ++half) {
            const int rloc = wm * 32 + mt * 16 + half * 8 + g;
            if (bm < 64) {
                const int rr = bm * BM + rloc;
                const int b = rr >> 8, tt = rr & 255;
                float* dst = out + ((size_t)b * OUT_ROWS + 254 + tt) * D_ + n0 + wn * 64;
                #pragma unroll
                for (int nt = 0; nt < 8; ++nt) {
                    float2 v = make_float2(c[mt][nt][half * 2], c[mt][nt][half * 2 + 1]);
                    *reinterpret_cast<float2*>(dst + nt * 8 + t * 2) = v;
                }
            } else {
                const int rr = (bm - 64) * BM + rloc;   // compressed-memory row
                if (rr < CM_ROWS) {
                    float* dst0 = out + (size_t)rr * D_ + n0 + wn * 64;
                    #pragma unroll
                    for (int nt = 0; nt < 8; ++nt) {
                        float2 v = make_float2(c[mt][nt][half * 2], c[mt][nt][half * 2 + 1]);
                        float* dp = dst0 + nt * 8 + t * 2;
                        for (int b = 0; b < BATCH; ++b)
                            *reinterpret_cast<float2*>(dp + (size_t)b * OUT_ROWS * D_) = v;
                    }
                }
            }
        }
    }
}

// ---------------------------------------------------------------------------
extern "C" void kernel_launch(void* const* d_in, const int* in_sizes, int n_in,
                              void* d_out, int out_size)
{
    const float* inputs  = (const float*)d_in[0];  // (32, 512, 1024)
    const float* memory  = (const float*)d_in[1];  // (2558, 1024)
    const float* filters = (const float*)d_in[2];  // (2, 1024, 1024)
    float* out = (float*)d_out;                    // (32, 2558, 1024)

    cudaFuncSetAttribute(mega, cudaFuncAttributeMaxDynamicSharedMemorySize,
                         SMEM_BYTES);

    // merged prep: A/B fp16 conversions + x passthrough (one launch)
    prep<<<PREP_BLOCKS, 256>>>(inputs, memory, filters, out);

    // GEMM blocks first, copy blocks last (backfill wave-2 slack)
    mega<<<TOTAL_BLOCKS, 256, SMEM_BYTES>>>(memory, out);
}

// round 14
// speedup vs baseline: 1.2749x; 1.1590x over previous
#include <cuda_runtime.h>
#include <cuda_fp16.h>
#include <cstdint>

// ============================================================================
// HelixMemory (R13 + cm-tiles-first block order):
//   out[b, 0:254]      = cm[r]   = memory[2r+2] @ F0 + memory[2r+3] @ F1
//   out[b, 254:510]    = cx[b,t] = x[b,2t] @ F0 + x[b,2t+1] @ F1
//   out[b, 510:2046]   = memory[1022:2558]
//   out[b, 2046:2558]  = x[b]
// kernel 1: prep (merged): conv_AB (g_Ah fp16 + x passthrough) + conv_filters
//           (g_Bt[n][k] fp16).
// kernel 2: mega: blocks [0,16) = cm GEMM tiles (heavy 32x-broadcast epilogue
//           -> issued FIRST so their store traffic overlaps later GEMM work),
//           blocks [16,528) = input GEMM tiles, blocks [528,792) = tail copy
//           CTAs (memory broadcast, unroll-8).
// ============================================================================

namespace {
constexpr int D_       = 1024;
constexpr int KDIM     = 2048;
constexpr int OUT_ROWS = 2558;
constexpr int CM_ROWS  = 254;
constexpr int BATCH    = 32;
constexpr int SEQ      = 512;

constexpr int M_ROWS = BATCH * 256 + 256;        // 8448 A rows

constexpr int BM = 128, BN = 128, BK = 64;       // BK in fp16 elements
constexpr int STAGES = 3;
constexpr int KT = KDIM / BK;                    // 32

constexpr int PITCH_H  = BK + 8;                 // 72 halves = 144 B pitch
constexpr int TILE_H   = BM * PITCH_H;           // 9216 halves
constexpr int STAGE_H  = 2 * TILE_H;             // A + B
constexpr int SMEM_BYTES = STAGES * STAGE_H * 2; // 110592 B -> occ 2

constexpr int CM_TILES     = 2 * 8;              // bm 64,65 x 8 bn
constexpr int GEMM_BLOCKS  = 8 * 66;             // 528
constexpr int COPY_CTAS    = 264;
constexpr int TOTAL_BLOCKS = GEMM_BLOCKS + COPY_CTAS;  // 792

// prep kernel block split
constexpr int AB_BLOCKS   = 1184;                // conv_AB part
constexpr int FILT_BLOCKS = (D_ / 32) * (KDIM / 64);   // 1024
constexpr int PREP_BLOCKS = AB_BLOCKS + FILT_BLOCKS;   // 2208

// copy space: memory-tail broadcast (float4 units)
constexpr int BCST_PER_B = 1536 * D_ / 4;                          // 393216
constexpr int BCST_F4    = BATCH * BCST_PER_B;                     // 12,582,912
constexpr int COPY_CHUNK = (BCST_F4 + COPY_CTAS - 1) / COPY_CTAS;  // 47663
}

__device__ __align__(128) __half g_Ah[M_ROWS * KDIM];  // 34.6 MB fp16 A
__device__ __align__(128) __half g_Bt[D_ * KDIM];      // 4 MB filters^T [n][k]

// ---------------------------------------------------------------------------
__device__ __forceinline__ uint32_t smem_u32(const void* p) {
    uint32_t a;
    asm("{ .reg .u64 t; cvta.to.shared.u64 t, %1; cvt.u32.u64 %0, t; }" : "=r"(a) : "l"(p));
    return a;
}
__device__ __forceinline__ void cp16(uint32_t s, const void* g) {
    asm volatile("cp.async.cg.shared.global [%0], [%1], 16;" :: "r"(s), "l"(g));
}
__device__ __forceinline__ void ldsm_x4(uint32_t* r, uint32_t addr) {
    asm volatile("ldmatrix.sync.aligned.m8n8.x4.shared.b16 {%0,%1,%2,%3}, [%4];"
                 : "=r"(r[0]), "=r"(r[1]), "=r"(r[2]), "=r"(r[3]) : "r"(addr));
}
__device__ __forceinline__ void mma_f16(float* c, const uint32_t* a, const uint32_t* b) {
    asm volatile(
        "mma.sync.aligned.m16n8k16.row.col.f32.f16.f16.f32 "
        "{%0,%1,%2,%3}, {%4,%5,%6,%7}, {%8,%9}, {%0,%1,%2,%3};"
        : "+f"(c[0]), "+f"(c[1]), "+f"(c[2]), "+f"(c[3])
        : "r"(a[0]), "r"(a[1]), "r"(a[2]), "r"(a[3]), "r"(b[0]), "r"(b[1]));
}
__device__ __forceinline__ uint32_t pack_h2(float x, float y) {
    __half2 h = __floats2half2_rn(x, y);
    return *reinterpret_cast<uint32_t*>(&h);
}

// ---------------------------------------------------------------------------
// prep (merged): blocks [0,1184): conv_AB; blocks [1184,2208): conv_filters
// ---------------------------------------------------------------------------
__global__ __launch_bounds__(256) void prep(
    const float* __restrict__ inputs, const float* __restrict__ memory,
    const float* __restrict__ F, float* __restrict__ out)
{
    const int blk = blockIdx.x;
    const int tid = threadIdx.x;

    if (blk < AB_BLOCKS) {
        constexpr int IN_F4 = BATCH * SEQ * D_ / 4;     // 4,194,304
        constexpr int TOTAL = M_ROWS * KDIM / 4;        // 4,325,376
        uint2* ah = reinterpret_cast<uint2*>(g_Ah);
        const float4* in4  = reinterpret_cast<const float4*>(inputs);
        const float4* mem4 = reinterpret_cast<const float4*>(memory + 2 * D_);
        float4* out4 = reinterpret_cast<float4*>(out);

        for (int idx = blk * 256 + tid; idx < TOTAL; idx += AB_BLOCKS * 256) {
            float4 v;
            if (idx < IN_F4) {
                v = in4[idx];
                const int b = idx >> 17;                // / 131072
                const int rem = idx & 131071;
                out4[(size_t)b * (OUT_ROWS * D_ / 4) + 2046 * (D_ / 4) + rem] = v;
            } else {
                v = mem4[idx - IN_F4];
            }
            ah[idx] = make_uint2(pack_h2(v.x, v.y), pack_h2(v.z, v.w));
        }
    } else {
        __shared__ float tile[64][33];
        const int cid = blk - AB_BLOCKS;                // 0..1023
        const int n0 = (cid & 31) * 32;
        const int k0 = (cid >> 5) * 64;
        const int tx = tid & 31, ty = tid >> 5;         // 32 x 8
        #pragma unroll
        for (int i = ty; i < 64; i += 8)
            tile[i][tx] = F[(size_t)(k0 + i) * D_ + n0 + tx];
        __syncthreads();
        uint32_t* bt = reinterpret_cast<uint32_t*>(g_Bt);
        #pragma unroll
        for (int i = ty; i < 32; i += 8)
            bt[(size_t)(n0 + i) * (KDIM / 2) + k0 / 2 + tx] =
                pack_h2(tile[2 * tx][i], tile[2 * tx + 1][i]);
    }
}

// ---------------------------------------------------------------------------
// copy CTA body: out[b, 510:2046] = memory[1022:2558]; unroll-8 for MLP.
// ---------------------------------------------------------------------------
__device__ __forceinline__ void copy_body(
    int cid, const float* __restrict__ memory, float* __restrict__ out)
{
    const float4* mem4 = reinterpret_cast<const float4*>(memory) + 1022 * (D_ / 4);
    float4*       out4 = reinterpret_cast<float4*>(out);

    const int base = cid * COPY_CHUNK;
    const int end  = (base + COPY_CHUNK < BCST_F4) ? base + COPY_CHUNK : BCST_F4;

    for (int t = base + threadIdx.x; t < end; t += 256 * 8) {
        float4 v[8];
        size_t dj[8];
        bool ok[8];
        #pragma unroll
        for (int u = 0; u < 8; ++u) {
            const int idx = t + u * 256;
            ok[u] = (idx < end);
            if (ok[u]) {
                const int b = idx / BCST_PER_B;
                const int rem = idx - b * BCST_PER_B;
                v[u]  = mem4[rem];
                dj[u] = (size_t)b * (OUT_ROWS * D_ / 4) + 510 * (D_ / 4) + rem;
            }
        }
        #pragma unroll
        for (int u = 0; u < 8; ++u)
            if (ok[u]) out4[dj[u]] = v[u];
    }
}

// ---------------------------------------------------------------------------
// mega: blocks [0,16) = cm tiles (heavy epilogue, issued first);
//       blocks [16,528) = input tiles; blocks [528,792) = copy CTAs.
// ---------------------------------------------------------------------------
__global__ __launch_bounds__(256, 2) void mega(
    const float* __restrict__ memory, float* __restrict__ out)
{
    const int blk = blockIdx.x;
    if (blk >= GEMM_BLOCKS) {
        copy_body(blk - GEMM_BLOCKS, memory, out);
        return;
    }
    // cm tiles first (bm 64,65), then input tiles (bm 0..63)
    int bm, bn;
    if (blk < CM_TILES) {
        bm = 64 + (blk >> 3);
        bn = blk & 7;
    } else {
        const int gid = blk - CM_TILES;
        bm = gid >> 3;
        bn = gid & 7;
    }
    const int n0 = bn * BN;

    extern __shared__ __half smem_h[];
    const uint32_t sbase = smem_u32(smem_h);

    const int tid  = threadIdx.x;
    const int wid  = tid >> 5;
    const int lane = tid & 31;
    const int g    = lane >> 2;
    const int t    = lane & 3;
    const int wm   = wid & 3;                   // 4 warps x 32 rows
    const int wn   = wid >> 2;                  // 2 warps x 64 cols

    // ldmatrix lane->row mappings
    const int a_row = lane & 15;                // m within 16
    const int a_k   = (lane >> 4) << 3;         // k offset 0/8
    const int b_row = (lane & 7) + ((lane >> 4) << 3);   // n within 16
    const int b_k   = ((lane >> 3) & 1) << 3;   // k offset 0/8

    const uint32_t aoff0 = (uint32_t)((wm * 32 + a_row) * PITCH_H + a_k) * 2;
    const uint32_t boff0 = (uint32_t)TILE_H * 2 +
                           (uint32_t)((wn * 64 + b_row) * PITCH_H + b_k) * 2;

    const __half* Abase = g_Ah + (size_t)bm * BM * KDIM;

    auto issue = [&](int kt) {
        const int s = kt % STAGES;
        const uint32_t sA = sbase + (uint32_t)(s * STAGE_H) * 2;
        const uint32_t sB = sA + (uint32_t)TILE_H * 2;
        const int k0 = kt * BK;
        #pragma unroll
        for (int i = 0; i < 4; ++i) {           // 1024 16B chunks per tile
            const int q   = tid + 256 * i;
            const int row = q >> 3;
            const int c   = q & 7;
            cp16(sA + (uint32_t)(row * PITCH_H + c * 8) * 2,
                 Abase + (size_t)row * KDIM + k0 + c * 8);
            cp16(sB + (uint32_t)(row * PITCH_H + c * 8) * 2,
                 g_Bt + (size_t)(n0 + row) * KDIM + k0 + c * 8);
        }
        asm volatile("cp.async.commit_group;" ::: "memory");
    };

    float c[2][8][4] = {};

    issue(0);
    issue(1);

    for (int kt = 0; kt < KT; ++kt) {
        asm volatile("cp.async.wait_group 1;" ::: "memory");
        __syncthreads();

        if (kt + STAGES - 1 < KT) issue(kt + STAGES - 1);

        const int s = kt % STAGES;
        const uint32_t stg = sbase + (uint32_t)(s * STAGE_H) * 2;

        #pragma unroll
        for (int ks = 0; ks < 4; ++ks) {        // 4 x k16 = BK 64
            const uint32_t kb = (uint32_t)(ks * 16) * 2;   // k byte offset

            uint32_t a[2][4];
            #pragma unroll
            for (int mt = 0; mt < 2; ++mt)
                ldsm_x4(a[mt], stg + aoff0 + (uint32_t)(mt * 16 * PITCH_H) * 2 + kb);

            uint32_t bf[8][2];
            #pragma unroll
            for (int nb = 0; nb < 4; ++nb) {    // 4 x n16 = 64 cols
                uint32_t r[4];
                ldsm_x4(r, stg + boff0 + (uint32_t)(nb * 16 * PITCH_H) * 2 + kb);
                bf[2 * nb][0]     = r[0];
                bf[2 * nb][1]     = r[1];
                bf[2 * nb + 1][0] = r[2];
                bf[2 * nb + 1][1] = r[3];
            }
            #pragma unroll
            for (int mt = 0; mt < 2; ++mt)
                #pragma unroll
                for (int nt = 0; nt < 8; ++nt)
                    mma_f16(c[mt][nt], a[mt], bf[nt]);
        }
    }

    // ---- epilogue -----------------------------------------------------------
    #pragma unroll
    for (int mt = 0; mt < 2; ++mt) {
        #pragma unroll
        for (int half = 0; half < 2; ++half) {
            const int rloc = wm * 32 + mt * 16 + half * 8 + g;
            if (bm < 64) {
                const int rr = bm * BM + rloc;
                const int b = rr >> 8, tt = rr & 255;
                float* dst = out + ((size_t)b * OUT_ROWS + 254 + tt) * D_ + n0 + wn * 64;
                #pragma unroll
                for (int nt = 0; nt < 8; ++nt) {
                    float2 v = make_float2(c[mt][nt][half * 2], c[mt][nt][half * 2 + 1]);
                    *reinterpret_cast<float2*>(dst + nt * 8 + t * 2) = v;
                }
            } else {
                const int rr = (bm - 64) * BM + rloc;   // compressed-memory row
                if (rr < CM_ROWS) {
                    float* dst0 = out + (size_t)rr * D_ + n0 + wn * 64;
                    #pragma unroll
                    for (int nt = 0; nt < 8; ++nt) {
                        float2 v = make_float2(c[mt][nt][half * 2], c[mt][nt][half * 2 + 1]);
                        float* dp = dst0 + nt * 8 + t * 2;
                        for (int b = 0; b < BATCH; ++b)
                            *reinterpret_cast<float2*>(dp + (size_t)b * OUT_ROWS * D_) = v;
                    }
                }
            }
        }
    }
}

// ---------------------------------------------------------------------------
extern "C" void kernel_launch(void* const* d_in, const int* in_sizes, int n_in,
                              void* d_out, int out_size)
{
    const float* inputs  = (const float*)d_in[0];  // (32, 512, 1024)
    const float* memory  = (const float*)d_in[1];  // (2558, 1024)
    const float* filters = (const float*)d_in[2];  // (2, 1024, 1024)
    float* out = (float*)d_out;                    // (32, 2558, 1024)

    cudaFuncSetAttribute(mega, cudaFuncAttributeMaxDynamicSharedMemorySize,
                         SMEM_BYTES);

    // merged prep: A/B fp16 conversions + x passthrough (one launch)
    prep<<<PREP_BLOCKS, 256>>>(inputs, memory, filters, out);

    // cm tiles first, then input tiles, copy blocks last
    mega<<<TOTAL_BLOCKS, 256, SMEM_BYTES>>>(memory, out);
}